// round 4
// baseline (speedup 1.0000x reference)
#include <cuda_runtime.h>
#include <cuda_fp16.h>
#include <cstdint>

// LUTBlock: out[b,o] = sum_{t=0..15} table[t, idx[b,t], o]
// idx[b,t] = sum_c ((x[b, aa[t,c]] - x[b, ab[t,c]]) > 0) << c
//
// R4: smem-staged x (kills divergent L1 gather wavefronts), ballot-based
// index computation (1 comparison per thread), 2 batches per CTA for 2x MLP
// in the table-read stream. Table pre-converted to fp16 scratch (R3 win).

#define B_SZ    16384
#define IN_F    1024
#define OUT_F   1024
#define T_CNT   16
#define C_CNT   8
#define R_CNT   256

#define TABLE_ELEMS (T_CNT * R_CNT * OUT_F)   // 4M elements

// 8 MB fp16 scratch copy of the table (device global: allocation-free).
__device__ __half g_table_h[TABLE_ELEMS];

// ---------------------------------------------------------------------------
// Pre-pass: fp32 table -> fp16 scratch. 4M elems, float4 in / half2x2 out.
// ---------------------------------------------------------------------------
__global__ __launch_bounds__(256)
void convert_table_kernel(const float4* __restrict__ table4)
{
    const int i = blockIdx.x * blockDim.x + threadIdx.x;   // 0 .. 1M-1
    const float4 v = __ldg(&table4[i]);
    half2* dst = reinterpret_cast<half2*>(g_table_h) + 2 * i;
    dst[0] = __floats2half2_rn(v.x, v.y);
    dst[1] = __floats2half2_rn(v.z, v.w);
}

// ---------------------------------------------------------------------------
// Main: one CTA per 2 batches. 256 threads.
//   Phase 0: coalesced-stage both x rows into smem (float4).
//   Phase 1: one comparison per thread (2 batches * 16 t * 8 c = 256),
//            ballot -> 8-bit index fields.
//   Phase 2: thread tid owns output float4 group `tid` for BOTH batches:
//            2x16 independent 8-byte fp16 table loads, fp32 accumulation.
// ---------------------------------------------------------------------------
__global__ __launch_bounds__(256)
void lut_gather_sum2_kernel(const float4* __restrict__ x4,
                            const int* __restrict__ aa,
                            const int* __restrict__ ab,
                            float4* __restrict__ out4)
{
    __shared__ float s_x[2][IN_F];
    __shared__ int   s_idx[2][T_CNT];

    const int tid = threadIdx.x;
    const int b0  = blockIdx.x * 2;
    const int b1  = b0 + 1;

    // Phase 0: stage both x rows (each row = 256 float4).
    {
        float4 v0 = __ldg(&x4[(size_t)b0 * (IN_F / 4) + tid]);
        float4 v1 = __ldg(&x4[(size_t)b1 * (IN_F / 4) + tid]);
        reinterpret_cast<float4*>(s_x[0])[tid] = v0;
        reinterpret_cast<float4*>(s_x[1])[tid] = v1;
    }
    __syncthreads();

    // Phase 1: comparison (bsel, t, c) = (tid>>7, (tid>>3)&15, tid&7).
    {
        const int bsel = tid >> 7;          // 0..1
        const int i128 = tid & 127;         // t*8 + c
        const int lane = tid & 31;
        const int ia = __ldg(&aa[i128]);
        const int ib = __ldg(&ab[i128]);
        const float d = s_x[bsel][ia] - s_x[bsel][ib];
        const unsigned m = __ballot_sync(0xFFFFFFFFu, d > 0.0f);
        // each warp holds 4 t-groups of 8 lanes; lane%8==0 publishes its byte
        if ((lane & 7) == 0) {
            const int t = i128 >> 3;        // 0..15
            s_idx[bsel][t] = (m >> (lane & 24)) & 0xFF;
        }
    }
    __syncthreads();

    // Phase 2: gather-sum from fp16 table, two independent streams.
    const uint2* th = reinterpret_cast<const uint2*>(g_table_h);

    float4 a0 = make_float4(0.f, 0.f, 0.f, 0.f);
    float4 a1 = make_float4(0.f, 0.f, 0.f, 0.f);
#pragma unroll
    for (int t = 0; t < T_CNT; t++) {
        const int r0 = s_idx[0][t];
        const int r1 = s_idx[1][t];
        const uint2 v0 = __ldg(&th[(((t << 8) + r0) << 8) + tid]);
        const uint2 v1 = __ldg(&th[(((t << 8) + r1) << 8) + tid]);

        const float2 f0a = __half22float2(*reinterpret_cast<const half2*>(&v0.x));
        const float2 f0b = __half22float2(*reinterpret_cast<const half2*>(&v0.y));
        a0.x += f0a.x; a0.y += f0a.y; a0.z += f0b.x; a0.w += f0b.y;

        const float2 f1a = __half22float2(*reinterpret_cast<const half2*>(&v1.x));
        const float2 f1b = __half22float2(*reinterpret_cast<const half2*>(&v1.y));
        a1.x += f1a.x; a1.y += f1a.y; a1.z += f1b.x; a1.w += f1b.y;
    }

    out4[(size_t)b0 * (OUT_F / 4) + tid] = a0;
    out4[(size_t)b1 * (OUT_F / 4) + tid] = a1;
}

extern "C" void kernel_launch(void* const* d_in, const int* in_sizes, int n_in,
                              void* d_out, int out_size)
{
    const float4* x4     = (const float4*)d_in[0];  // (B, IN_F) fp32
    const float4* table4 = (const float4*)d_in[1];  // (T, R, OUT_F) fp32
    const int*    aa     = (const int*)   d_in[2];  // (T, C) int32
    const int*    ab     = (const int*)   d_in[3];  // (T, C) int32
    float4*       out4   = (float4*)      d_out;    // (B, OUT_F) fp32

    (void)in_sizes; (void)n_in; (void)out_size;

    // Pre-pass: table -> fp16 scratch
    convert_table_kernel<<<TABLE_ELEMS / 4 / 256, 256>>>(table4);

    // Main gather-sum, 2 batches per CTA
    lut_gather_sum2_kernel<<<B_SZ / 2, 256>>>(x4, aa, ab, out4);
}

// round 6
// speedup vs baseline: 1.1164x; 1.1164x over previous
#include <cuda_runtime.h>
#include <cuda_fp16.h>
#include <cstdint>

// LUTBlock: out[b,o] = sum_{t=0..15} table[t, idx[b,t], o]
// idx[b,t] = sum_c ((x[b, aa[t,c]] - x[b, ab[t,c]]) > 0) << c
//
// R6 (= R5 with compile fix): R3 structure (1 batch/CTA, occ=8) + staged-x
// ballot phase 1. fp16 table scratch, wide pre-pass.

#define B_SZ    16384
#define IN_F    1024
#define OUT_F   1024
#define T_CNT   16
#define C_CNT   8
#define R_CNT   256

#define TABLE_ELEMS (T_CNT * R_CNT * OUT_F)   // 4M elements

// 8 MB fp16 scratch copy of the table (device global: allocation-free).
__device__ __half g_table_h[TABLE_ELEMS];

// ---------------------------------------------------------------------------
// Pre-pass: fp32 table -> fp16 scratch. Each thread: 8 elems (32B in, 16B out).
// ---------------------------------------------------------------------------
__global__ __launch_bounds__(256)
void convert_table_kernel(const float4* __restrict__ table4)
{
    const int i = blockIdx.x * blockDim.x + threadIdx.x;   // 0 .. 512K-1
    const float4 v0 = __ldg(&table4[2 * i + 0]);
    const float4 v1 = __ldg(&table4[2 * i + 1]);
    half2 h[4];
    h[0] = __floats2half2_rn(v0.x, v0.y);
    h[1] = __floats2half2_rn(v0.z, v0.w);
    h[2] = __floats2half2_rn(v1.x, v1.y);
    h[3] = __floats2half2_rn(v1.z, v1.w);
    reinterpret_cast<uint4*>(g_table_h)[i] = *reinterpret_cast<const uint4*>(h);
}

// ---------------------------------------------------------------------------
// Main: one CTA per batch, 256 threads, <=32 regs (occ 8 CTAs/SM).
//   Phase 0: coalesced stage of x row (4KB) into smem.
//   Phase 1: 128 threads, one comparison each, ballot -> 16 indices.
//   Phase 2: thread tid owns out float4 group tid; 16 independent 8B fp16
//            table loads, fp32 accumulate, one STG.128.
// ---------------------------------------------------------------------------
__global__ __launch_bounds__(256, 8)
void lut_gather_sum_kernel(const float4* __restrict__ x4,
                           const int* __restrict__ aa,
                           const int* __restrict__ ab,
                           float4* __restrict__ out4)
{
    __shared__ float s_x[IN_F];
    __shared__ int   s_idx[T_CNT];

    const int tid = threadIdx.x;
    const int b   = blockIdx.x;

    // Phase 0: stage x row (256 x float4 = 4KB, fully coalesced).
    reinterpret_cast<float4*>(s_x)[tid] = __ldg(&x4[(size_t)b * (IN_F / 4) + tid]);
    __syncthreads();

    // Phase 1: threads 0..127 each do one comparison (t = tid>>3, c = tid&7).
    if (tid < 128) {
        const int lane = tid & 31;
        const int ia = __ldg(&aa[tid]);
        const int ib = __ldg(&ab[tid]);
        const float d = s_x[ia] - s_x[ib];
        const unsigned m = __ballot_sync(0xFFFFFFFFu, d > 0.0f);
        // each warp covers 4 t-groups of 8 lanes; lane%8==0 publishes its byte
        if ((lane & 7) == 0) {
            s_idx[tid >> 3] = (m >> (lane & 24)) & 0xFF;
        }
    }
    __syncthreads();

    // Phase 2: gather-sum from fp16 table (L2-resident), fp32 accumulation.
    const uint2* th = reinterpret_cast<const uint2*>(g_table_h);

    float4 acc = make_float4(0.f, 0.f, 0.f, 0.f);
#pragma unroll
    for (int t = 0; t < T_CNT; t++) {
        const int r = s_idx[t];
        const uint2 v = __ldg(&th[(((t << 8) + r) << 8) + tid]);
        const float2 f0 = __half22float2(*reinterpret_cast<const half2*>(&v.x));
        const float2 f1 = __half22float2(*reinterpret_cast<const half2*>(&v.y));
        acc.x += f0.x;
        acc.y += f0.y;
        acc.z += f1.x;
        acc.w += f1.y;
    }

    out4[(size_t)b * (OUT_F / 4) + tid] = acc;
}

extern "C" void kernel_launch(void* const* d_in, const int* in_sizes, int n_in,
                              void* d_out, int out_size)
{
    const float4* x4     = (const float4*)d_in[0];  // (B, IN_F) fp32
    const float4* table4 = (const float4*)d_in[1];  // (T, R, OUT_F) fp32
    const int*    aa     = (const int*)   d_in[2];  // (T, C) int32
    const int*    ab     = (const int*)   d_in[3];  // (T, C) int32
    float4*       out4   = (float4*)      d_out;    // (B, OUT_F) fp32

    (void)in_sizes; (void)n_in; (void)out_size;

    // Pre-pass: table -> fp16 scratch (8 elems per thread)
    convert_table_kernel<<<TABLE_ELEMS / 8 / 256, 256>>>(table4);

    // Main gather-sum, 1 batch per CTA
    lut_gather_sum_kernel<<<B_SZ, 256>>>(x4, aa, ab, out4);
}

// round 7
// speedup vs baseline: 1.1341x; 1.0159x over previous
#include <cuda_runtime.h>
#include <cuda_fp16.h>
#include <cstdint>

// LUTBlock: out[b,o] = sum_{t=0..15} table[t, idx[b,t], o]
// idx[b,t] = sum_c ((x[b, aa[t,c]] - x[b, ab[t,c]]) > 0) << c
//
// R7: ballot words ARE the packed index bytes -> one STS.32/warp, one
// broadcast LDS.128 hoists all 16 indices (kills 128 in-loop LDS wf/CTA).
// Packed f32x2 accumulation (FADD2). fp16 table scratch (R3).

#define B_SZ    16384
#define IN_F    1024
#define OUT_F   1024
#define T_CNT   16
#define C_CNT   8
#define R_CNT   256

#define TABLE_ELEMS (T_CNT * R_CNT * OUT_F)   // 4M elements

// 8 MB fp16 scratch copy of the table (device global: allocation-free).
__device__ __half g_table_h[TABLE_ELEMS];

// ---------------------------------------------------------------------------
// Pre-pass: fp32 table -> fp16 scratch. Each thread: 8 elems (32B in, 16B out).
// ---------------------------------------------------------------------------
__global__ __launch_bounds__(256)
void convert_table_kernel(const float4* __restrict__ table4)
{
    const int i = blockIdx.x * blockDim.x + threadIdx.x;   // 0 .. 512K-1
    const float4 v0 = __ldg(&table4[2 * i + 0]);
    const float4 v1 = __ldg(&table4[2 * i + 1]);
    half2 h[4];
    h[0] = __floats2half2_rn(v0.x, v0.y);
    h[1] = __floats2half2_rn(v0.z, v0.w);
    h[2] = __floats2half2_rn(v1.x, v1.y);
    h[3] = __floats2half2_rn(v1.z, v1.w);
    reinterpret_cast<uint4*>(g_table_h)[i] = *reinterpret_cast<const uint4*>(h);
}

// ---------------------------------------------------------------------------
// Main: one CTA per batch, 256 threads, <=32 regs (occ 8 CTAs/SM).
//   Phase 0: coalesced stage of x row (4KB) into smem.
//   Phase 1: 128 threads, one comparison each; warp w's ballot word is the
//            packed 4 index bytes for t=4w..4w+3 -> one STS.32 per warp.
//   Phase 2: hoist all 16 indices via one broadcast LDS.128; per t:
//            PRMT extract + LDG.64 + 4 CVT + 2 packed f32x2 adds.
// ---------------------------------------------------------------------------
__global__ __launch_bounds__(256, 8)
void lut_gather_sum_kernel(const float4* __restrict__ x4,
                           const int* __restrict__ aa,
                           const int* __restrict__ ab,
                           float4* __restrict__ out4)
{
    __shared__ float s_x[IN_F];
    __shared__ __align__(16) unsigned s_pk[4];

    const int tid = threadIdx.x;
    const int b   = blockIdx.x;

    // Phase 0: stage x row (256 x float4 = 4KB, fully coalesced).
    reinterpret_cast<float4*>(s_x)[tid] = __ldg(&x4[(size_t)b * (IN_F / 4) + tid]);
    __syncthreads();

    // Phase 1: threads 0..127 each do one comparison (t = tid>>3, c = tid&7).
    // Warp w's ballot bits [8k+c] correspond to (t = 4w+k, c): the 32-bit
    // ballot word is exactly the 4 packed index bytes for t = 4w..4w+3.
    if (tid < 128) {
        const int lane = tid & 31;
        const int ia = __ldg(&aa[tid]);
        const int ib = __ldg(&ab[tid]);
        const float d = s_x[ia] - s_x[ib];
        const unsigned m = __ballot_sync(0xFFFFFFFFu, d > 0.0f);
        if (lane == 0) s_pk[tid >> 5] = m;
    }
    __syncthreads();

    // Phase 2: gather-sum from fp16 table (L2-resident).
    uint4 pk = *reinterpret_cast<const uint4*>(s_pk);   // all 16 index bytes
    const char* base = reinterpret_cast<const char*>(g_table_h) + tid * 8;

    unsigned long long a0 = 0ull, a1 = 0ull;   // packed (f32,f32) accumulators
#pragma unroll
    for (int t = 0; t < T_CNT; t++) {
        const unsigned w = (t < 4) ? pk.x : (t < 8) ? pk.y : (t < 12) ? pk.z : pk.w;
        const unsigned r = __byte_perm(w, 0u, 0x4440 + (t & 3));   // index byte
        // byte offset: t * (256 rows * 2048 B) + r * 2048 ; t-part is a
        // compile-time constant folded into the LDG immediate.
        const uint2 v = __ldg(reinterpret_cast<const uint2*>(
                                  base + (size_t)t * 524288u + r * 2048u));
        const float2 f0 = __half22float2(*reinterpret_cast<const half2*>(&v.x));
        const float2 f1 = __half22float2(*reinterpret_cast<const half2*>(&v.y));
        unsigned long long p0, p1;
        asm("mov.b64 %0, {%1, %2};" : "=l"(p0) : "f"(f0.x), "f"(f0.y));
        asm("mov.b64 %0, {%1, %2};" : "=l"(p1) : "f"(f1.x), "f"(f1.y));
        asm("add.rn.f32x2 %0, %0, %1;" : "+l"(a0) : "l"(p0));
        asm("add.rn.f32x2 %0, %0, %1;" : "+l"(a1) : "l"(p1));
    }

    float4 acc;
    asm("mov.b64 {%0, %1}, %2;" : "=f"(acc.x), "=f"(acc.y) : "l"(a0));
    asm("mov.b64 {%0, %1}, %2;" : "=f"(acc.z), "=f"(acc.w) : "l"(a1));
    out4[(size_t)b * (OUT_F / 4) + tid] = acc;
}

extern "C" void kernel_launch(void* const* d_in, const int* in_sizes, int n_in,
                              void* d_out, int out_size)
{
    const float4* x4     = (const float4*)d_in[0];  // (B, IN_F) fp32
    const float4* table4 = (const float4*)d_in[1];  // (T, R, OUT_F) fp32
    const int*    aa     = (const int*)   d_in[2];  // (T, C) int32
    const int*    ab     = (const int*)   d_in[3];  // (T, C) int32
    float4*       out4   = (float4*)      d_out;    // (B, OUT_F) fp32

    (void)in_sizes; (void)n_in; (void)out_size;

    // Pre-pass: table -> fp16 scratch (8 elems per thread)
    convert_table_kernel<<<TABLE_ELEMS / 8 / 256, 256>>>(table4);

    // Main gather-sum, 1 batch per CTA
    lut_gather_sum_kernel<<<B_SZ, 256>>>(x4, aa, ab, out4);
}

// round 8
// speedup vs baseline: 1.1990x; 1.0573x over previous
#include <cuda_runtime.h>
#include <cuda_fp16.h>
#include <cstdint>

// LUTBlock: out[b,o] = sum_{t=0..15} table[t, idx[b,t], o]
// idx[b,t] = sum_c ((x[b, aa[t,c]] - x[b, ab[t,c]]) > 0) << c
//
// R8: pairwise fp16 pre-accumulation (HADD2) halves convert/add work and
// removes the ALU packing MOVs of R7. Ballot-packed indices (R7), fp16
// table scratch (R3), staged-x phase 1 (R6).

#define B_SZ    16384
#define IN_F    1024
#define OUT_F   1024
#define T_CNT   16
#define C_CNT   8
#define R_CNT   256

#define TABLE_ELEMS (T_CNT * R_CNT * OUT_F)   // 4M elements

// 8 MB fp16 scratch copy of the table (device global: allocation-free).
__device__ __half g_table_h[TABLE_ELEMS];

// ---------------------------------------------------------------------------
// Pre-pass: fp32 table -> fp16 scratch. Each thread: 8 elems (32B in, 16B out).
// ---------------------------------------------------------------------------
__global__ __launch_bounds__(256)
void convert_table_kernel(const float4* __restrict__ table4)
{
    const int i = blockIdx.x * blockDim.x + threadIdx.x;   // 0 .. 512K-1
    const float4 v0 = __ldg(&table4[2 * i + 0]);
    const float4 v1 = __ldg(&table4[2 * i + 1]);
    half2 h[4];
    h[0] = __floats2half2_rn(v0.x, v0.y);
    h[1] = __floats2half2_rn(v0.z, v0.w);
    h[2] = __floats2half2_rn(v1.x, v1.y);
    h[3] = __floats2half2_rn(v1.z, v1.w);
    reinterpret_cast<uint4*>(g_table_h)[i] = *reinterpret_cast<const uint4*>(h);
}

// ---------------------------------------------------------------------------
// Main: one CTA per batch, 256 threads, <=32 regs (occ 8 CTAs/SM).
//   Phase 0: coalesced stage of x row (4KB) into smem.
//   Phase 1: 128 threads, one comparison each; warp w's ballot word is the
//            packed 4 index bytes for t=4w..4w+3 -> one STS.32 per warp.
//   Phase 2: t processed in pairs: 2x LDG.64, HADD2 fp16 pre-sum, 4 CVT,
//            4 scalar FADD into fp32 accumulators. One STG.128.
// ---------------------------------------------------------------------------
__global__ __launch_bounds__(256, 8)
void lut_gather_sum_kernel(const float4* __restrict__ x4,
                           const int* __restrict__ aa,
                           const int* __restrict__ ab,
                           float4* __restrict__ out4)
{
    __shared__ float s_x[IN_F];
    __shared__ __align__(16) unsigned s_pk[4];

    const int tid = threadIdx.x;
    const int b   = blockIdx.x;

    // Phase 0: stage x row (256 x float4 = 4KB, fully coalesced).
    reinterpret_cast<float4*>(s_x)[tid] = __ldg(&x4[(size_t)b * (IN_F / 4) + tid]);
    __syncthreads();

    // Phase 1: threads 0..127 each do one comparison (t = tid>>3, c = tid&7).
    // Warp w's ballot bits [8k+c] correspond to (t = 4w+k, c): the 32-bit
    // ballot word is exactly the 4 packed index bytes for t = 4w..4w+3.
    if (tid < 128) {
        const int lane = tid & 31;
        const int ia = __ldg(&aa[tid]);
        const int ib = __ldg(&ab[tid]);
        const float d = s_x[ia] - s_x[ib];
        const unsigned m = __ballot_sync(0xFFFFFFFFu, d > 0.0f);
        if (lane == 0) s_pk[tid >> 5] = m;
    }
    __syncthreads();

    // Phase 2: gather-sum from fp16 table (L2-resident).
    uint4 pk = *reinterpret_cast<const uint4*>(s_pk);   // all 16 index bytes
    const char* base = reinterpret_cast<const char*>(g_table_h) + tid * 8;

    float4 acc = make_float4(0.f, 0.f, 0.f, 0.f);
#pragma unroll
    for (int tp = 0; tp < T_CNT / 2; tp++) {
        const int t0 = 2 * tp;
        const int t1 = 2 * tp + 1;
        const unsigned wd = (tp < 2) ? pk.x : (tp < 4) ? pk.y : (tp < 6) ? pk.z : pk.w;
        const unsigned r0 = __byte_perm(wd, 0u, 0x4440 + (t0 & 3));
        const unsigned r1 = __byte_perm(wd, 0u, 0x4440 + (t1 & 3));
        // byte offset: t * (256 rows * 2048 B) + r * 2048 (t-part folds into
        // the LDG immediate).
        const uint2 v0 = __ldg(reinterpret_cast<const uint2*>(
                                   base + (size_t)t0 * 524288u + r0 * 2048u));
        const uint2 v1 = __ldg(reinterpret_cast<const uint2*>(
                                   base + (size_t)t1 * 524288u + r1 * 2048u));
        // fp16 pairwise pre-sum (exact inputs, one rounding per lane-pair)
        const half2 s0 = __hadd2(*reinterpret_cast<const half2*>(&v0.x),
                                 *reinterpret_cast<const half2*>(&v1.x));
        const half2 s1 = __hadd2(*reinterpret_cast<const half2*>(&v0.y),
                                 *reinterpret_cast<const half2*>(&v1.y));
        const float2 f0 = __half22float2(s0);
        const float2 f1 = __half22float2(s1);
        acc.x += f0.x;
        acc.y += f0.y;
        acc.z += f1.x;
        acc.w += f1.y;
    }

    out4[(size_t)b * (OUT_F / 4) + tid] = acc;
}

extern "C" void kernel_launch(void* const* d_in, const int* in_sizes, int n_in,
                              void* d_out, int out_size)
{
    const float4* x4     = (const float4*)d_in[0];  // (B, IN_F) fp32
    const float4* table4 = (const float4*)d_in[1];  // (T, R, OUT_F) fp32
    const int*    aa     = (const int*)   d_in[2];  // (T, C) int32
    const int*    ab     = (const int*)   d_in[3];  // (T, C) int32
    float4*       out4   = (float4*)      d_out;    // (B, OUT_F) fp32

    (void)in_sizes; (void)n_in; (void)out_size;

    // Pre-pass: table -> fp16 scratch (8 elems per thread)
    convert_table_kernel<<<TABLE_ELEMS / 8 / 256, 256>>>(table4);

    // Main gather-sum, 1 batch per CTA
    lut_gather_sum_kernel<<<B_SZ, 256>>>(x4, aa, ab, out4);
}